// round 5
// baseline (speedup 1.0000x reference)
#include <cuda_runtime.h>
#include <math.h>

#define HD     1024
#define NROWS  50000
#define NCTA   576            // 4 CTAs/SM on >=144 SMs: co-resident
#define WPC    4              // warps per CTA
#define NTHR   128
#define TOTW   (NCTA * WPC)   // 2304 warps
#define NP4    256            // float4 per 1024-float vector

// Scratch (__device__ globals)
__device__ float   g_q[HD];
__device__ float   g_d2[HD];                 // W2@h_t + b2
__device__ float4  g_epartT[NP4 * NCTA];     // [position][cta]
__device__ float   g_Zpart[NCTA];
__device__ float   g_es[HD];
__device__ float   g_Zsum;
__device__ unsigned g_ctr[3];                // monotonic barrier counters

// Grid barrier, graph-replay safe (counter never resets).
__device__ __forceinline__ void gbar(int k) {
    __syncthreads();
    if (threadIdx.x == 0) {
        __threadfence();
        unsigned old = atomicAdd(&g_ctr[k], 1u);
        unsigned tgt = old - (old % NCTA) + NCTA;
        while (*(volatile unsigned*)&g_ctr[k] < tgt) __nanosleep(32);
    }
    __syncthreads();
    __threadfence();
}

__device__ __forceinline__ void cpa16(unsigned dst, const void* src) {
    asm volatile("cp.async.cg.shared.global [%0], [%1], 16;\n" :: "r"(dst), "l"(src));
}
__device__ __forceinline__ void cp_commit() { asm volatile("cp.async.commit_group;\n"); }
template<int N> __device__ __forceinline__ void cp_wait() {
    asm volatile("cp.async.wait_group %0;\n" :: "n"(N));
}

__global__ __launch_bounds__(NTHR, 4) void fused(
    const float* __restrict__ H,  const float* __restrict__ ht,
    const float* __restrict__ W0, const float* __restrict__ b0,
    const float* __restrict__ W1, const float* __restrict__ b1,
    const float* __restrict__ W2, const float* __restrict__ b2,
    float* __restrict__ out)
{
    __shared__ float4 s_buf[WPC][2][NP4];    // 32 KB: per-warp double row buffers
    __shared__ float4 sv[NP4];               // 4 KB: ht / reduce buf / e_s
    __shared__ float  sZ[WPC];
    __shared__ float  sred[NTHR];
    __shared__ float  sZtot;

    const int tid = threadIdx.x, wid = tid >> 5, lane = tid & 31;
    const int cta = blockIdx.x;

    // ------------- Phase 1: q = W0@ht + b0 ; d2 = W2@ht + b2 ----------------
    sv[tid]       = ((const float4*)ht)[tid];
    sv[tid + 128] = ((const float4*)ht)[tid + 128];
    __syncthreads();
    {
        int gw = cta * WPC + wid;                  // 0..2303; 2048 rows of work
        if (gw < 2048) {
            int j = gw & 1023;
            const float* W = (gw < 1024) ? W0 : W2;
            const float* b = (gw < 1024) ? b0 : b2;
            const float4* wr = (const float4*)(W + (size_t)j * HD);
            float4 w[8];
#pragma unroll
            for (int k = 0; k < 8; k++) w[k] = wr[lane + 32 * k];   // MLP=8
            float s = 0.f;
#pragma unroll
            for (int k = 0; k < 8; k++) {
                float4 h4 = sv[lane + 32 * k];
                s = fmaf(w[k].x, h4.x, s); s = fmaf(w[k].y, h4.y, s);
                s = fmaf(w[k].z, h4.z, s); s = fmaf(w[k].w, h4.w, s);
            }
#pragma unroll
            for (int o = 16; o; o >>= 1) s += __shfl_xor_sync(0xffffffffu, s, o);
            if (lane == 0) { if (gw < 1024) g_q[j] = s + b[j]; else g_d2[j] = s + b[j]; }
        }
    }
    gbar(0);

    // ------------- Phase 2: single pass over H, cp.async double-buffered ----
    float4 q4[8];
#pragma unroll
    for (int k = 0; k < 8; k++)
        q4[k] = __ldcg(((const float4*)g_q) + lane + 32 * k);

    float4 e[8];
#pragma unroll
    for (int k = 0; k < 8; k++) e[k] = make_float4(0.f, 0.f, 0.f, 0.f);
    float Z = 0.f;

    const float4* bufp[2] = { &s_buf[wid][0][0], &s_buf[wid][1][0] };
    unsigned bufa[2];
    bufa[0] = (unsigned)__cvta_generic_to_shared(bufp[0]);
    bufa[1] = bufa[0] + NP4 * 16;

    int row = cta * WPC + wid;
    {   // prologue: stage first row into buffer 0
        const float* src = H + (size_t)row * HD;
#pragma unroll
        for (int k = 0; k < 8; k++)
            cpa16(bufa[0] + (lane + 32 * k) * 16, src + (lane + 32 * k) * 4);
        cp_commit();
    }
    int stage = 0;
    for (; row < NROWS; row += TOTW) {
        int nxt = row + TOTW;
        if (nxt < NROWS) {                         // stage next row into other buf
            const float* src = H + (size_t)nxt * HD;
#pragma unroll
            for (int k = 0; k < 8; k++)
                cpa16(bufa[stage ^ 1] + (lane + 32 * k) * 16, src + (lane + 32 * k) * 4);
        }
        cp_commit();
        cp_wait<1>();                              // current row's group complete

        float4 r[8];
#pragma unroll
        for (int k = 0; k < 8; k++) r[k] = bufp[stage][lane + 32 * k];

        float s = 0.f;
#pragma unroll
        for (int k = 0; k < 8; k++) {
            s = fmaf(r[k].x, q4[k].x, s); s = fmaf(r[k].y, q4[k].y, s);
            s = fmaf(r[k].z, q4[k].z, s); s = fmaf(r[k].w, q4[k].w, s);
        }
#pragma unroll
        for (int o = 16; o; o >>= 1) s += __shfl_xor_sync(0xffffffffu, s, o);

        // double exp; softmax(t)=exp(t)/sum(exp(t)) exactly, t bounded.
        float u = expf(expf(s));
        Z += u;
#pragma unroll
        for (int k = 0; k < 8; k++) {
            e[k].x = fmaf(u, r[k].x, e[k].x);
            e[k].y = fmaf(u, r[k].y, e[k].y);
            e[k].z = fmaf(u, r[k].z, e[k].z);
            e[k].w = fmaf(u, r[k].w, e[k].w);
        }
        stage ^= 1;
    }
    cp_wait<0>();
    __syncthreads();                               // row buffers now dead

    // overlay warp partials on the (dead) row buffers: sw[4][256]
    {
        float4 (*sw)[NP4] = (float4 (*)[NP4])&s_buf[0][0][0];
#pragma unroll
        for (int k = 0; k < 8; k++) sw[wid][lane + 32 * k] = e[k];
        if (lane == 0) sZ[wid] = Z;
        __syncthreads();

#pragma unroll
        for (int h = 0; h < 2; h++) {              // each thread: 2 positions
            int p = tid + 128 * h;
            float4 a = sw[0][p];
#pragma unroll
            for (int w = 1; w < WPC; w++) {
                float4 v = sw[w][p];
                a.x += v.x; a.y += v.y; a.z += v.z; a.w += v.w;
            }
            g_epartT[p * NCTA + cta] = a;          // position-major
        }
        if (tid == 0)
            g_Zpart[cta] = sZ[0] + sZ[1] + sZ[2] + sZ[3];
    }
    gbar(1);

    // ------------- Phase 3: deterministic reduce over NCTA partials ---------
    if (cta < 256) {                               // one CTA per float4 position
        const float4* src = g_epartT + (size_t)cta * NCTA;
        float4 a = make_float4(0.f, 0.f, 0.f, 0.f);
        for (int b = tid; b < NCTA; b += NTHR) {
            float4 v = __ldcg(src + b);
            a.x += v.x; a.y += v.y; a.z += v.z; a.w += v.w;
        }
        sv[tid] = a;
        __syncthreads();
#pragma unroll
        for (int o = 64; o; o >>= 1) {
            if (tid < o) {
                float4 b = sv[tid + o], t = sv[tid];
                t.x += b.x; t.y += b.y; t.z += b.z; t.w += b.w;
                sv[tid] = t;
            }
            __syncthreads();
        }
        if (tid == 0) ((float4*)g_es)[cta] = sv[0];
    } else if (cta == 256) {                       // partition function
        float z = 0.f;
        for (int b = tid; b < NCTA; b += NTHR) z += __ldcg(g_Zpart + b);
        sred[tid] = z;
        __syncthreads();
#pragma unroll
        for (int o = 64; o; o >>= 1) {
            if (tid < o) sred[tid] += sred[tid + o];
            __syncthreads();
        }
        if (tid == 0) g_Zsum = sred[0];
    }
    gbar(2);

    // ------------- Phase 4: out = tanh(W1@e_s/Z + b1 + d2) ------------------
    if (cta < 256) {
        int j = cta * WPC + wid;                   // 0..1023
        const float4* w1r = (const float4*)(W1 + (size_t)j * HD);
        float4 a[8];
#pragma unroll
        for (int k = 0; k < 8; k++) a[k] = w1r[lane + 32 * k];   // MLP=8

        sv[tid]       = __ldcg(((const float4*)g_es) + tid);
        sv[tid + 128] = __ldcg(((const float4*)g_es) + tid + 128);
        if (tid == 0) sZtot = __ldcg(&g_Zsum);
        __syncthreads();

        float d1 = 0.f;
#pragma unroll
        for (int k = 0; k < 8; k++) {
            float4 v = sv[lane + 32 * k];
            d1 = fmaf(a[k].x, v.x, d1); d1 = fmaf(a[k].y, v.y, d1);
            d1 = fmaf(a[k].z, v.z, d1); d1 = fmaf(a[k].w, v.w, d1);
        }
#pragma unroll
        for (int o = 16; o; o >>= 1) d1 += __shfl_xor_sync(0xffffffffu, d1, o);
        if (lane == 0)
            out[j] = tanhf(d1 / sZtot + b1[j] + __ldcg(g_d2 + j));
    }
}

// ---------------------------------------------------------------------------
extern "C" void kernel_launch(void* const* d_in, const int* in_sizes, int n_in,
                              void* d_out, int out_size) {
    const float* H  = (const float*)d_in[0];
    const float* ht = (const float*)d_in[1];
    const float* W0 = (const float*)d_in[2];
    const float* b0 = (const float*)d_in[3];
    const float* W1 = (const float*)d_in[4];
    const float* b1 = (const float*)d_in[5];
    const float* W2 = (const float*)d_in[6];
    const float* b2 = (const float*)d_in[7];
    float* out = (float*)d_out;

    fused<<<NCTA, NTHR>>>(H, ht, W0, b0, W1, b1, W2, b2, out);
}

// round 6
// speedup vs baseline: 1.1358x; 1.1358x over previous
#include <cuda_runtime.h>
#include <math.h>

#define HD      1024
#define NROWS   50000
#define GRID    288                  // 2 CTAs/SM on >=144 SMs: co-residency safe
#define WARPS_B 8
#define TOT_WARPS (GRID * WARPS_B)   // 2304
#define NP4     (HD / 4)             // 256 float4 per vector

// Scratch (__device__ globals)
__device__ float  g_q[HD];
__device__ float  g_d2[HD];                     // W2@h_t + b2
__device__ float4 g_epartT[NP4 * GRID];         // [position][cta]
__device__ float  g_Zpart[GRID];
__device__ float  g_es[HD];
__device__ float  g_Zsum;
__device__ unsigned g_ctr[4];                   // barrier counters (monotonic)

// Grid-wide barrier, graph-replay safe: counter never resets.
__device__ __forceinline__ void gbar(int k) {
    __syncthreads();
    if (threadIdx.x == 0) {
        __threadfence();
        unsigned old = atomicAdd(&g_ctr[k], 1u);
        unsigned target = old - (old % GRID) + GRID;
        while (*(volatile unsigned*)&g_ctr[k] < target) __nanosleep(32);
    }
    __syncthreads();
    __threadfence();
}

__device__ __forceinline__ float4 ldcs4(const float4* p) {
    float4 v;
    asm volatile("ld.global.cs.v4.f32 {%0,%1,%2,%3}, [%4];"
                 : "=f"(v.x), "=f"(v.y), "=f"(v.z), "=f"(v.w) : "l"(p));
    return v;
}

__global__ __launch_bounds__(256, 2) void fused(
    const float* __restrict__ H,  const float* __restrict__ ht,
    const float* __restrict__ W0, const float* __restrict__ b0,
    const float* __restrict__ W1, const float* __restrict__ b1,
    const float* __restrict__ W2, const float* __restrict__ b2,
    float* __restrict__ out)
{
    __shared__ float4 sv[NP4];                 // ht -> q -> e_s (reused per phase)
    __shared__ float4 se[WARPS_B][NP4];        // warp partials / reduce buf
    __shared__ float  sZ[WARPS_B];
    __shared__ float  sZr[256];
    __shared__ float  sZtot;

    const int tid  = threadIdx.x;
    const int wid  = tid >> 5, lane = tid & 31;
    const int cta  = blockIdx.x;

    // ---------------- Phase 1: q = W0@ht + b0 ; d2 = W2@ht + b2 --------------
    sv[tid] = ((const float4*)ht)[tid];
    __syncthreads();
    {
        int gw = cta * WARPS_B + wid;          // 0..2303 ; 2048 rows of work
        if (gw < 2048) {
            int j = gw & 1023;
            const float* W = (gw < 1024) ? W0 : W2;
            const float* b = (gw < 1024) ? b0 : b2;
            const float4* wr = (const float4*)(W + (size_t)j * HD);
            float4 w[8];
#pragma unroll
            for (int k = 0; k < 8; k++) w[k] = wr[lane + 32 * k];  // MLP=8
            float s = 0.f;
#pragma unroll
            for (int k = 0; k < 8; k++) {
                float4 h4 = sv[lane + 32 * k];
                s = fmaf(w[k].x, h4.x, s); s = fmaf(w[k].y, h4.y, s);
                s = fmaf(w[k].z, h4.z, s); s = fmaf(w[k].w, h4.w, s);
            }
#pragma unroll
            for (int o = 16; o; o >>= 1) s += __shfl_xor_sync(0xffffffffu, s, o);
            if (lane == 0) { if (gw < 1024) g_q[j] = s + b[j]; else g_d2[j] = s + b[j]; }
        }
    }
    gbar(0);

    // ---------------- Phase 2: pass over H, TWO rows per iteration -----------
    sv[tid] = __ldcg(((const float4*)g_q) + tid);
    __syncthreads();

    float4 e[8];
#pragma unroll
    for (int k = 0; k < 8; k++) e[k] = make_float4(0.f, 0.f, 0.f, 0.f);
    float Z = 0.f;

    const int gw = cta * WARPS_B + wid;
    // rows (2*gw, 2*gw+1), stride 2*TOT_WARPS. NROWS even & base even =>
    // row+1 is always valid when row is.
    for (int row = 2 * gw; row < NROWS; row += 2 * TOT_WARPS) {
        const float4* h0 = (const float4*)(H + (size_t)row * HD);
        const float4* h1 = (const float4*)(H + (size_t)(row + 1) * HD);

        float4 r0[8], r1[8];
#pragma unroll
        for (int k = 0; k < 8; k++) r0[k] = ldcs4(h0 + lane + 32 * k);  // 16 loads
#pragma unroll
        for (int k = 0; k < 8; k++) r1[k] = ldcs4(h1 + lane + 32 * k);  // front-batched

        float s0 = 0.f, s1 = 0.f;
#pragma unroll
        for (int k = 0; k < 8; k++) {
            float4 q4 = sv[lane + 32 * k];
            s0 = fmaf(r0[k].x, q4.x, s0); s0 = fmaf(r0[k].y, q4.y, s0);
            s0 = fmaf(r0[k].z, q4.z, s0); s0 = fmaf(r0[k].w, q4.w, s0);
            s1 = fmaf(r1[k].x, q4.x, s1); s1 = fmaf(r1[k].y, q4.y, s1);
            s1 = fmaf(r1[k].z, q4.z, s1); s1 = fmaf(r1[k].w, q4.w, s1);
        }
        // interleaved shuffle chains: the two 5-step latencies overlap
#pragma unroll
        for (int o = 16; o; o >>= 1) {
            s0 += __shfl_xor_sync(0xffffffffu, s0, o);
            s1 += __shfl_xor_sync(0xffffffffu, s1, o);
        }

        // double exp; softmax(t)=exp(t)/sum(exp(t)) exactly, t bounded.
        float u0 = expf(expf(s0));
        float u1 = expf(expf(s1));
        Z += u0 + u1;
#pragma unroll
        for (int k = 0; k < 8; k++) {
            e[k].x = fmaf(u0, r0[k].x, fmaf(u1, r1[k].x, e[k].x));
            e[k].y = fmaf(u0, r0[k].y, fmaf(u1, r1[k].y, e[k].y));
            e[k].z = fmaf(u0, r0[k].z, fmaf(u1, r1[k].z, e[k].z));
            e[k].w = fmaf(u0, r0[k].w, fmaf(u1, r1[k].w, e[k].w));
        }
    }

    // CTA-level deterministic reduce of the 8 warp partials
#pragma unroll
    for (int k = 0; k < 8; k++) se[wid][lane + 32 * k] = e[k];
    if (lane == 0) sZ[wid] = Z;
    __syncthreads();
    {
        float4 acc = se[0][tid];
#pragma unroll
        for (int w = 1; w < WARPS_B; w++) {
            float4 v = se[w][tid];
            acc.x += v.x; acc.y += v.y; acc.z += v.z; acc.w += v.w;
        }
        g_epartT[tid * GRID + cta] = acc;      // position-major for phase 3
        if (tid == 0) {
            float z = 0.f;
#pragma unroll
            for (int w = 0; w < WARPS_B; w++) z += sZ[w];
            g_Zpart[cta] = z;
        }
    }
    gbar(1);

    // ---------------- Phase 3: deterministic reduce over 288 partials --------
    if (cta < 256) {                           // one CTA per float4 position
        float4* red = &se[0][0];
        const float4* src = g_epartT + (size_t)cta * GRID;
        float4 a = __ldcg(src + tid);
        if (tid < GRID - 256) {
            float4 b = __ldcg(src + 256 + tid);
            a.x += b.x; a.y += b.y; a.z += b.z; a.w += b.w;
        }
        red[tid] = a;
        __syncthreads();
#pragma unroll
        for (int o = 128; o; o >>= 1) {
            if (tid < o) {
                float4 b = red[tid + o];
                float4 t = red[tid];
                t.x += b.x; t.y += b.y; t.z += b.z; t.w += b.w;
                red[tid] = t;
            }
            __syncthreads();
        }
        if (tid == 0) ((float4*)g_es)[cta] = red[0];
    } else if (cta == 256) {                   // partition function
        float z = (tid < GRID) ? __ldcg(g_Zpart + tid) : 0.f;
        if (tid < GRID - 256) z += __ldcg(g_Zpart + 256 + tid);
        sZr[tid] = z;
        __syncthreads();
#pragma unroll
        for (int o = 128; o; o >>= 1) {
            if (tid < o) sZr[tid] += sZr[tid + o];
            __syncthreads();
        }
        if (tid == 0) g_Zsum = sZr[0];
    }
    gbar(2);

    // ---------------- Phase 4: out = tanh(W1@e_s/Z + b1 + d2) ----------------
    if (cta < 128) {
        int j = cta * WARPS_B + wid;           // 0..1023
        const float4* w1r = (const float4*)(W1 + (size_t)j * HD);
        float4 a[8];
#pragma unroll
        for (int k = 0; k < 8; k++) a[k] = w1r[lane + 32 * k];  // MLP=8

        sv[tid] = __ldcg(((const float4*)g_es) + tid);
        if (tid == 0) sZtot = __ldcg(&g_Zsum);
        __syncthreads();

        float d1 = 0.f;
#pragma unroll
        for (int k = 0; k < 8; k++) {
            float4 v = sv[lane + 32 * k];
            d1 = fmaf(a[k].x, v.x, d1); d1 = fmaf(a[k].y, v.y, d1);
            d1 = fmaf(a[k].z, v.z, d1); d1 = fmaf(a[k].w, v.w, d1);
        }
#pragma unroll
        for (int o = 16; o; o >>= 1) d1 += __shfl_xor_sync(0xffffffffu, d1, o);
        if (lane == 0)
            out[j] = tanhf(d1 / sZtot + b1[j] + __ldcg(g_d2 + j));
    }
}

// ---------------------------------------------------------------------------
extern "C" void kernel_launch(void* const* d_in, const int* in_sizes, int n_in,
                              void* d_out, int out_size) {
    const float* H  = (const float*)d_in[0];
    const float* ht = (const float*)d_in[1];
    const float* W0 = (const float*)d_in[2];
    const float* b0 = (const float*)d_in[3];
    const float* W1 = (const float*)d_in[4];
    const float* b1 = (const float*)d_in[5];
    const float* W2 = (const float*)d_in[6];
    const float* b2 = (const float*)d_in[7];
    float* out = (float*)d_out;

    fused<<<GRID, 256>>>(H, ht, W0, b0, W1, b1, W2, b2, out);
}